// round 1
// baseline (speedup 1.0000x reference)
#include <cuda_runtime.h>
#include <math.h>

#define D_MODEL 1024
#define NHEADS  16
#define DH      64
#define SEQ     2048
#define BATCH   2
#define WIN     128
#define MROWS   (BATCH * SEQ)   // 4096

// Scratch buffers (static device memory — allowed; no runtime allocation)
__device__ float g_q [MROWS * D_MODEL];
__device__ float g_k [MROWS * D_MODEL];
__device__ float g_v [MROWS * D_MODEL];
__device__ float g_ao[MROWS * D_MODEL];

// ---------------------------------------------------------------------------
// GEMM: C[M,N] = A[M,K] * W[N,K]^T + bias[N]   (M=4096, N=K=1024)
// 128x128 block tile, 256 threads, 8x8 per-thread microtile, K-step 16.
// mode: 0/1/2 -> C = g_q/g_k/g_v, A = A_param (x)
//       3     -> A = g_ao, C = C_param (d_out)
// ---------------------------------------------------------------------------
__global__ __launch_bounds__(256, 2)
void gemm_nt_bias(const float* __restrict__ A_param,
                  const float* __restrict__ W,
                  const float* __restrict__ bias,
                  float* __restrict__ C_param,
                  int mode)
{
    const int K = D_MODEL;
    __shared__ float sA[16][128];
    __shared__ float sB[16][128];

    const float* A;
    float* C;
    if (mode == 0)      { A = A_param; C = g_q; }
    else if (mode == 1) { A = A_param; C = g_k; }
    else if (mode == 2) { A = A_param; C = g_v; }
    else                { A = g_ao;    C = C_param; }

    int tid = threadIdx.x;
    int bm = blockIdx.y * 128;
    int bn = blockIdx.x * 128;
    int tx = tid & 15;          // n-tile index (8 cols each)
    int ty = tid >> 4;          // m-tile index (8 rows each)
    int lr = tid >> 1;          // load row 0..127
    int lc = (tid & 1) << 3;    // load col offset 0 or 8

    const float* Ap = A + (bm + lr) * K + lc;
    const float* Wp = W + (bn + lr) * K + lc;

    float acc[8][8];
#pragma unroll
    for (int i = 0; i < 8; i++)
#pragma unroll
        for (int j = 0; j < 8; j++) acc[i][j] = 0.f;

    for (int kt = 0; kt < K; kt += 16) {
        float4 a0 = *(const float4*)(Ap + kt);
        float4 a1 = *(const float4*)(Ap + kt + 4);
        float4 b0 = *(const float4*)(Wp + kt);
        float4 b1 = *(const float4*)(Wp + kt + 4);

        __syncthreads();   // previous tile compute done
        sA[lc + 0][lr] = a0.x; sA[lc + 1][lr] = a0.y;
        sA[lc + 2][lr] = a0.z; sA[lc + 3][lr] = a0.w;
        sA[lc + 4][lr] = a1.x; sA[lc + 5][lr] = a1.y;
        sA[lc + 6][lr] = a1.z; sA[lc + 7][lr] = a1.w;
        sB[lc + 0][lr] = b0.x; sB[lc + 1][lr] = b0.y;
        sB[lc + 2][lr] = b0.z; sB[lc + 3][lr] = b0.w;
        sB[lc + 4][lr] = b1.x; sB[lc + 5][lr] = b1.y;
        sB[lc + 6][lr] = b1.z; sB[lc + 7][lr] = b1.w;
        __syncthreads();

#pragma unroll
        for (int k = 0; k < 16; k++) {
            float ar[8], br[8];
            *(float4*)(ar)     = *(const float4*)&sA[k][ty * 8];
            *(float4*)(ar + 4) = *(const float4*)&sA[k][ty * 8 + 4];
            *(float4*)(br)     = *(const float4*)&sB[k][tx * 8];
            *(float4*)(br + 4) = *(const float4*)&sB[k][tx * 8 + 4];
#pragma unroll
            for (int i = 0; i < 8; i++)
#pragma unroll
                for (int j = 0; j < 8; j++)
                    acc[i][j] += ar[i] * br[j];
        }
    }

#pragma unroll
    for (int i = 0; i < 8; i++) {
        int row = bm + ty * 8 + i;
#pragma unroll
        for (int j = 0; j < 8; j += 4) {
            float4 o;
            o.x = acc[i][j + 0] + bias[bn + tx * 8 + j + 0];
            o.y = acc[i][j + 1] + bias[bn + tx * 8 + j + 1];
            o.z = acc[i][j + 2] + bias[bn + tx * 8 + j + 2];
            o.w = acc[i][j + 3] + bias[bn + tx * 8 + j + 3];
            *(float4*)&C[row * D_MODEL + bn + tx * 8 + j] = o;
        }
    }
}

// ---------------------------------------------------------------------------
// RoPE (in-place on g_q, g_k) + q scale by Dh^-0.5.
// grid = B*S blocks, 512 threads: thread -> (head = tid/32, pair-lane j = tid%32)
// ---------------------------------------------------------------------------
__global__ __launch_bounds__(512)
void rope_kernel()
{
    int bs = blockIdx.x;             // b*SEQ + s
    int s  = bs & (SEQ - 1);
    int h  = threadIdx.x >> 5;
    int j  = threadIdx.x & 31;

    // inv_freq = 10000^(-j/32);  log2(10000) = 13.287712379549449
    float inv = exp2f(-(float)j * (13.2877123795494f / 32.f));
    float ang = (float)s * inv;
    float sn, cs;
    sincosf(ang, &sn, &cs);

    int base = bs * D_MODEL + h * DH;
    float q1 = g_q[base + j], q2 = g_q[base + j + 32];
    g_q[base + j]      = (q1 * cs - q2 * sn) * 0.125f;
    g_q[base + j + 32] = (q1 * sn + q2 * cs) * 0.125f;
    float k1 = g_k[base + j], k2 = g_k[base + j + 32];
    g_k[base + j]      = k1 * cs - k2 * sn;
    g_k[base + j + 32] = k1 * sn + k2 * cs;
}

// ---------------------------------------------------------------------------
// Sliding-window attention (flash-style, fp32).
// Block = 256 threads handles 64 queries of one (b, h).
// Keys chunked by 32; all tiles in shared memory; online softmax.
// ---------------------------------------------------------------------------
__global__ __launch_bounds__(256)
void attn_kernel()
{
    __shared__ float sQt[64][68];     // [d][q], padded
    __shared__ float sKt[64][34];     // [d][k], padded (float2-aligned)
    __shared__ float sV [32][64];     // [k][d]
    __shared__ float sP [64][33];     // scores/probs [q][k]
    __shared__ float sm[64], sl[64], sscale[64];

    int tid = threadIdx.x;
    int q0 = blockIdx.x * 64;
    int h  = blockIdx.y;
    int b  = blockIdx.z;

    const float* Q  = g_q + (size_t)b * SEQ * D_MODEL + h * DH;
    const float* Kp = g_k + (size_t)b * SEQ * D_MODEL + h * DH;
    const float* Vp = g_v + (size_t)b * SEQ * D_MODEL + h * DH;

    // Load Q tile (64 x 64), transposed into sQt
#pragma unroll
    for (int i = 0; i < 4; i++) {
        int lin = i * 1024 + tid * 4;
        int row = lin >> 6, col = lin & 63;
        float4 qv = *(const float4*)&Q[(q0 + row) * D_MODEL + col];
        sQt[col + 0][row] = qv.x; sQt[col + 1][row] = qv.y;
        sQt[col + 2][row] = qv.z; sQt[col + 3][row] = qv.w;
    }
    if (tid < 64) { sm[tid] = -1e30f; sl[tid] = 0.f; }

    int tx = tid & 15;   // score: 2 keys each | pv: 4 dims each
    int ty = tid >> 4;   // 4 queries each
    float acc[4][4];
#pragma unroll
    for (int i = 0; i < 4; i++)
#pragma unroll
        for (int j = 0; j < 4; j++) acc[i][j] = 0.f;

    int kv0 = q0 - WIN; if (kv0 < 0) kv0 = 0;
    int nk  = q0 + 64 - kv0;   // 64, 128, or 192 (always multiple of 32)

    for (int kb = 0; kb < nk; kb += 32) {
        int kbase = kv0 + kb;

        // Stage K/V chunk through registers
        float4 kvec[2], vvec[2];
        int krow[2], kcol[2];
#pragma unroll
        for (int i = 0; i < 2; i++) {
            int lin = i * 1024 + tid * 4;
            krow[i] = lin >> 6; kcol[i] = lin & 63;
            kvec[i] = *(const float4*)&Kp[(kbase + krow[i]) * D_MODEL + kcol[i]];
            vvec[i] = *(const float4*)&Vp[(kbase + krow[i]) * D_MODEL + kcol[i]];
        }
        __syncthreads();   // previous PV phase done reading sV/sP
#pragma unroll
        for (int i = 0; i < 2; i++) {
            sKt[kcol[i] + 0][krow[i]] = kvec[i].x;
            sKt[kcol[i] + 1][krow[i]] = kvec[i].y;
            sKt[kcol[i] + 2][krow[i]] = kvec[i].z;
            sKt[kcol[i] + 3][krow[i]] = kvec[i].w;
            *(float4*)&sV[krow[i]][kcol[i]] = vvec[i];
        }
        __syncthreads();

        // ---- Score phase: S[64x32] = Q·K^T ----
        float sc[4][2] = {{0.f,0.f},{0.f,0.f},{0.f,0.f},{0.f,0.f}};
#pragma unroll
        for (int d = 0; d < 64; d++) {
            float4 qv  = *(const float4*)&sQt[d][ty * 4];
            float2 kv2 = *(const float2*)&sKt[d][tx * 2];
            sc[0][0] += qv.x * kv2.x; sc[0][1] += qv.x * kv2.y;
            sc[1][0] += qv.y * kv2.x; sc[1][1] += qv.y * kv2.y;
            sc[2][0] += qv.z * kv2.x; sc[2][1] += qv.z * kv2.y;
            sc[3][0] += qv.w * kv2.x; sc[3][1] += qv.w * kv2.y;
        }
#pragma unroll
        for (int i = 0; i < 4; i++) {
            int qg = q0 + ty * 4 + i;
#pragma unroll
            for (int j = 0; j < 2; j++) {
                int kg = kbase + tx * 2 + j;
                bool blocked = (kg > qg) || (kg < qg - WIN);
                sP[ty * 4 + i][tx * 2 + j] = blocked ? -1e30f : sc[i][j];
            }
        }
        __syncthreads();

        // ---- Online softmax (4 lanes per query row) ----
        {
            int r = tid >> 2, g = tid & 3;
            float v[8]; float mx = -1e30f;
#pragma unroll
            for (int u = 0; u < 8; u++) { v[u] = sP[r][g * 8 + u]; mx = fmaxf(mx, v[u]); }
            mx = fmaxf(mx, __shfl_xor_sync(0xffffffffu, mx, 1));
            mx = fmaxf(mx, __shfl_xor_sync(0xffffffffu, mx, 2));
            float mold = sm[r];
            float mnew = fmaxf(mold, mx);
            float sum = 0.f;
#pragma unroll
            for (int u = 0; u < 8; u++) {
                float p = (v[u] < -1e29f) ? 0.f : __expf(v[u] - mnew);
                sP[r][g * 8 + u] = p;
                sum += p;
            }
            sum += __shfl_xor_sync(0xffffffffu, sum, 1);
            sum += __shfl_xor_sync(0xffffffffu, sum, 2);
            if (g == 0) {
                float scl = __expf(mold - mnew);   // 0 if mold=-1e30, 1 if unchanged
                sl[r] = sl[r] * scl + sum;
                sm[r] = mnew;
                sscale[r] = scl;
            }
        }
        __syncthreads();

        // ---- PV phase: O += P·V ----
#pragma unroll
        for (int i = 0; i < 4; i++) {
            float scl = sscale[ty * 4 + i];
            acc[i][0] *= scl; acc[i][1] *= scl; acc[i][2] *= scl; acc[i][3] *= scl;
        }
#pragma unroll
        for (int k = 0; k < 32; k++) {
            float4 vv = *(const float4*)&sV[k][tx * 4];
#pragma unroll
            for (int i = 0; i < 4; i++) {
                float p = sP[ty * 4 + i][k];
                acc[i][0] += p * vv.x; acc[i][1] += p * vv.y;
                acc[i][2] += p * vv.z; acc[i][3] += p * vv.w;
            }
        }
    }

    // Normalize and write to g_ao in (B,S,D) layout
#pragma unroll
    for (int i = 0; i < 4; i++) {
        int qg = q0 + ty * 4 + i;
        float inv = 1.f / sl[ty * 4 + i];
        float4 o;
        o.x = acc[i][0] * inv; o.y = acc[i][1] * inv;
        o.z = acc[i][2] * inv; o.w = acc[i][3] * inv;
        *(float4*)&g_ao[((size_t)b * SEQ + qg) * D_MODEL + h * DH + tx * 4] = o;
    }
}

// ---------------------------------------------------------------------------
extern "C" void kernel_launch(void* const* d_in, const int* in_sizes, int n_in,
                              void* d_out, int out_size)
{
    const float* x  = (const float*)d_in[0];
    const float* Wq = (const float*)d_in[1];
    const float* bq = (const float*)d_in[2];
    const float* Wk = (const float*)d_in[3];
    const float* bk = (const float*)d_in[4];
    const float* Wv = (const float*)d_in[5];
    const float* bv = (const float*)d_in[6];
    const float* Wo = (const float*)d_in[7];
    const float* bo = (const float*)d_in[8];
    float* out = (float*)d_out;

    dim3 ggrid(D_MODEL / 128, MROWS / 128);   // (8, 32)
    gemm_nt_bias<<<ggrid, 256>>>(x, Wq, bq, nullptr, 0);
    gemm_nt_bias<<<ggrid, 256>>>(x, Wk, bk, nullptr, 1);
    gemm_nt_bias<<<ggrid, 256>>>(x, Wv, bv, nullptr, 2);

    rope_kernel<<<MROWS, 512>>>();

    dim3 agrid(SEQ / 64, NHEADS, BATCH);      // (32, 16, 2)
    attn_kernel<<<agrid, 256>>>();

    gemm_nt_bias<<<ggrid, 256>>>(nullptr, Wo, bo, out, 3);
}

// round 3
// speedup vs baseline: 1.7487x; 1.7487x over previous
#include <cuda_runtime.h>
#include <cuda_bf16.h>
#include <math.h>
#include <stdint.h>

#define D_MODEL 1024
#define NHEADS  16
#define DH      64
#define SEQ     2048
#define BATCH   2
#define WIN     128
#define MROWS   (BATCH * SEQ)   // 4096

// ---------------- scratch (static device memory) ----------------
__device__ float g_q [MROWS * D_MODEL];
__device__ float g_k [MROWS * D_MODEL];
__device__ float g_v [MROWS * D_MODEL];
__device__ float g_ao[MROWS * D_MODEL];

__device__ __nv_bfloat16 g_xh [MROWS * D_MODEL];
__device__ __nv_bfloat16 g_xl [MROWS * D_MODEL];
__device__ __nv_bfloat16 g_wh [4 * D_MODEL * D_MODEL];
__device__ __nv_bfloat16 g_wl [4 * D_MODEL * D_MODEL];
__device__ __nv_bfloat16 g_aoh[MROWS * D_MODEL];
__device__ __nv_bfloat16 g_aol[MROWS * D_MODEL];

// ---------------- PTX helpers (sm_80-era: valid on sm_100 plain target) ----
__device__ __forceinline__ uint32_t smem_u32(const void* p) {
    uint32_t a;
    asm("{ .reg .u64 t; cvta.to.shared.u64 t, %1; cvt.u32.u64 %0, t; }"
        : "=r"(a) : "l"(p));
    return a;
}
#define CPA16(dst, src) \
    asm volatile("cp.async.cg.shared.global [%0], [%1], 16;" :: "r"(dst), "l"(src))
#define CPA_COMMIT() asm volatile("cp.async.commit_group;" ::: "memory")
#define CPA_WAIT1()  asm volatile("cp.async.wait_group 1;" ::: "memory")
#define CPA_WAIT0()  asm volatile("cp.async.wait_group 0;" ::: "memory")

#define LDM4(r, addr) \
    asm volatile("ldmatrix.sync.aligned.m8n8.x4.shared.b16 {%0,%1,%2,%3}, [%4];" \
        : "=r"((r)[0]), "=r"((r)[1]), "=r"((r)[2]), "=r"((r)[3]) : "r"(addr))

#define MMA16816(acc, a, b0, b1) \
    asm volatile("mma.sync.aligned.m16n8k16.row.col.f32.bf16.bf16.f32 " \
        "{%0,%1,%2,%3}, {%4,%5,%6,%7}, {%8,%9}, {%0,%1,%2,%3};" \
        : "+f"((acc)[0]), "+f"((acc)[1]), "+f"((acc)[2]), "+f"((acc)[3]) \
        : "r"((a)[0]), "r"((a)[1]), "r"((a)[2]), "r"((a)[3]), "r"(b0), "r"(b1))

// ---------------------------------------------------------------------------
// fp32 -> bf16 hi/lo split.  which: 0=x, 1..4=Wq/Wk/Wv/Wo, 5=g_ao
// ---------------------------------------------------------------------------
__global__ __launch_bounds__(256)
void conv_split(const float* __restrict__ src_p, int which, int n4)
{
    int i = blockIdx.x * 256 + threadIdx.x;
    if (i >= n4) return;
    const float* src;
    __nv_bfloat16 *hi, *lo;
    if (which == 0)      { src = src_p; hi = g_xh; lo = g_xl; }
    else if (which <= 4) { src = src_p;
                           hi = g_wh + (size_t)(which - 1) * D_MODEL * D_MODEL;
                           lo = g_wl + (size_t)(which - 1) * D_MODEL * D_MODEL; }
    else                 { src = g_ao; hi = g_aoh; lo = g_aol; }

    float4 v = ((const float4*)src)[i];
    __nv_bfloat16 h0 = __float2bfloat16(v.x);
    __nv_bfloat16 h1 = __float2bfloat16(v.y);
    __nv_bfloat16 h2 = __float2bfloat16(v.z);
    __nv_bfloat16 h3 = __float2bfloat16(v.w);
    __nv_bfloat162 hh0 = {h0, h1}, hh1 = {h2, h3};
    ((__nv_bfloat162*)hi)[i * 2]     = hh0;
    ((__nv_bfloat162*)hi)[i * 2 + 1] = hh1;
    __nv_bfloat162 ll0 = {__float2bfloat16(v.x - __bfloat162float(h0)),
                          __float2bfloat16(v.y - __bfloat162float(h1))};
    __nv_bfloat162 ll1 = {__float2bfloat16(v.z - __bfloat162float(h2)),
                          __float2bfloat16(v.w - __bfloat162float(h3))};
    ((__nv_bfloat162*)lo)[i * 2]     = ll0;
    ((__nv_bfloat162*)lo)[i * 2 + 1] = ll1;
}

// ---------------------------------------------------------------------------
// mma.sync bf16-split GEMM: C[M,N] = A*W^T + bias, M=4096, N=K=1024.
// 128x128 CTA tile, 8 warps (64x32 each), K-chunks of 64, cp.async 2-stage.
// Tiles per stage: Ah, Al, Bh, Bl (each 128x64 bf16 = 16KB, SW128-swizzled).
// mode 0: A = g_xh/g_xl, W = g_wh/g_wl + z*1M, C = g_q/g_k/g_v by z.
// mode 1: A = g_aoh/g_aol, W idx 3, C = out_direct, bias = b0.
// ---------------------------------------------------------------------------
#define TILE_B 16384
#define STAGE_B 65536
#define SMEM_DYN (2 * STAGE_B + 1024)

__global__ __launch_bounds__(256, 1)
void gemm_tc(const float* __restrict__ b0, const float* __restrict__ b1,
             const float* __restrict__ b2, float* __restrict__ out_direct, int mode)
{
    extern __shared__ char dsm_raw[];
    char* sm = (char*)(((uintptr_t)dsm_raw + 1023) & ~(uintptr_t)1023);
    const uint32_t sb = smem_u32(sm);
    const int tid = threadIdx.x, wid = tid >> 5, lane = tid & 31;
    const int bn = blockIdx.x * 128, bm = blockIdx.y * 128, z = blockIdx.z;

    const __nv_bfloat16 *Ah, *Al, *Wh, *Wl;
    const float* bias;
    float* C;
    if (mode == 0) {
        Ah = g_xh; Al = g_xl;
        Wh = g_wh + (size_t)z * D_MODEL * D_MODEL;
        Wl = g_wl + (size_t)z * D_MODEL * D_MODEL;
        bias = (z == 0) ? b0 : ((z == 1) ? b1 : b2);
        C = (z == 0) ? g_q : ((z == 1) ? g_k : g_v);
    } else {
        Ah = g_aoh; Al = g_aol;
        Wh = g_wh + (size_t)3 * D_MODEL * D_MODEL;
        Wl = g_wl + (size_t)3 * D_MODEL * D_MODEL;
        bias = b0;
        C = out_direct;
    }

    // cp.async source mapping: thread -> row r = tid/2, col half (tid&1)*32,
    // 4 segments of 8 bf16 (16B each) per tile.
    const int r = tid >> 1;
    const int colb = (tid & 1) * 32;
    const __nv_bfloat16* srcs[4] = {
        Ah + (size_t)(bm + r) * D_MODEL + colb,
        Al + (size_t)(bm + r) * D_MODEL + colb,
        Wh + (size_t)(bn + r) * D_MODEL + colb,
        Wl + (size_t)(bn + r) * D_MODEL + colb };
    uint32_t sts_off[4];
#pragma unroll
    for (int s = 0; s < 4; s++) {
        uint32_t o = (uint32_t)r * 128 + (uint32_t)(colb + s * 8) * 2;
        sts_off[s] = o ^ (((uint32_t)r & 7) << 4);   // SW128
    }

    // warp tile origin
    const int wm = (wid & 1) * 64;
    const int wn = (wid >> 1) * 32;

    float acc[4][4][4];
#pragma unroll
    for (int mi = 0; mi < 4; mi++)
#pragma unroll
        for (int nj = 0; nj < 4; nj++)
#pragma unroll
            for (int q = 0; q < 4; q++) acc[mi][nj][q] = 0.f;

    // ldmatrix lane addressing precompute (row part + xor)
    const uint32_t lrow = lane & 15;          // row within 16-row tile
    const uint32_t lunit = (lane >> 4) * 16;  // 16B unit (k half)

    // prologue: issue chunk 0 into stage 0
#pragma unroll
    for (int t = 0; t < 4; t++)
#pragma unroll
        for (int s = 0; s < 4; s++)
            CPA16(sb + t * TILE_B + sts_off[s], srcs[t] + s * 8);
    CPA_COMMIT();

    for (int c = 0; c < 16; c++) {
        if (c + 1 < 16) {
            uint32_t stb = sb + (uint32_t)((c + 1) & 1) * STAGE_B;
#pragma unroll
            for (int t = 0; t < 4; t++)
#pragma unroll
                for (int s = 0; s < 4; s++)
                    CPA16(stb + t * TILE_B + sts_off[s], srcs[t] + (c + 1) * 64 + s * 8);
            CPA_COMMIT();
            CPA_WAIT1();
        } else {
            CPA_WAIT0();
        }
        __syncthreads();

        const uint32_t stg = sb + (uint32_t)(c & 1) * STAGE_B;
#pragma unroll
        for (int kk = 0; kk < 4; kk++) {
            // B fragments: 2 x (16 n-rows x k16) per split
            uint32_t bh[2][4], bl[2][4];
#pragma unroll
            for (int jp = 0; jp < 2; jp++) {
                uint32_t rw = (uint32_t)(wn + jp * 16) + lrow;
                uint32_t co = ((uint32_t)(kk * 32) + lunit) ^ ((rw & 7) << 4);
                uint32_t ab = stg + rw * 128 + co;
                LDM4(bh[jp], ab + 2 * TILE_B);
                LDM4(bl[jp], ab + 3 * TILE_B);
            }
#pragma unroll
            for (int mi = 0; mi < 4; mi++) {
                uint32_t ra = (uint32_t)(wm + mi * 16) + lrow;
                uint32_t co = ((uint32_t)(kk * 32) + lunit) ^ ((ra & 7) << 4);
                uint32_t aa = stg + ra * 128 + co;
                uint32_t ah[4], al[4];
                LDM4(ah, aa);
                LDM4(al, aa + TILE_B);
#pragma unroll
                for (int nj = 0; nj < 4; nj++) {
                    const int jp = nj >> 1, w = nj & 1;
                    MMA16816(acc[mi][nj], ah, bh[jp][w], bh[jp][w + 2]);
                    MMA16816(acc[mi][nj], ah, bl[jp][w], bl[jp][w + 2]);
                    MMA16816(acc[mi][nj], al, bh[jp][w], bh[jp][w + 2]);
                }
            }
        }
        __syncthreads();
    }

    // epilogue: acc (mi,nj): c0,c1 -> (row, col..col+1); c2,c3 -> row+8
#pragma unroll
    for (int mi = 0; mi < 4; mi++) {
        const int row = bm + wm + mi * 16 + (lane >> 2);
#pragma unroll
        for (int nj = 0; nj < 4; nj++) {
            const int col = bn + wn + nj * 8 + ((lane & 3) << 1);
            float2 o0 = { acc[mi][nj][0] + bias[col], acc[mi][nj][1] + bias[col + 1] };
            float2 o1 = { acc[mi][nj][2] + bias[col], acc[mi][nj][3] + bias[col + 1] };
            *(float2*)&C[(size_t)row * D_MODEL + col]       = o0;
            *(float2*)&C[(size_t)(row + 8) * D_MODEL + col] = o1;
        }
    }
}

// ---------------------------------------------------------------------------
// RoPE (in-place on g_q, g_k) + q scale by Dh^-0.5.
// ---------------------------------------------------------------------------
__global__ __launch_bounds__(512)
void rope_kernel()
{
    int bs = blockIdx.x;
    int s  = bs & (SEQ - 1);
    int h  = threadIdx.x >> 5;
    int j  = threadIdx.x & 31;

    float inv = exp2f(-(float)j * (13.2877123795494f / 32.f));
    float ang = (float)s * inv;
    float sn, cs;
    sincosf(ang, &sn, &cs);

    int base = bs * D_MODEL + h * DH;
    float q1 = g_q[base + j], q2 = g_q[base + j + 32];
    g_q[base + j]      = (q1 * cs - q2 * sn) * 0.125f;
    g_q[base + j + 32] = (q1 * sn + q2 * cs) * 0.125f;
    float k1 = g_k[base + j], k2 = g_k[base + j + 32];
    g_k[base + j]      = k1 * cs - k2 * sn;
    g_k[base + j + 32] = k1 * sn + k2 * cs;
}

// ---------------------------------------------------------------------------
// Sliding-window attention (flash-style, fp32).
// ---------------------------------------------------------------------------
__global__ __launch_bounds__(256)
void attn_kernel()
{
    __shared__ float sQt[64][68];
    __shared__ float sKt[64][34];
    __shared__ float sV [32][64];
    __shared__ float sP [64][33];
    __shared__ float sm[64], sl[64], sscale[64];

    int tid = threadIdx.x;
    int q0 = blockIdx.x * 64;
    int h  = blockIdx.y;
    int b  = blockIdx.z;

    const float* Q  = g_q + (size_t)b * SEQ * D_MODEL + h * DH;
    const float* Kp = g_k + (size_t)b * SEQ * D_MODEL + h * DH;
    const float* Vp = g_v + (size_t)b * SEQ * D_MODEL + h * DH;

#pragma unroll
    for (int i = 0; i < 4; i++) {
        int lin = i * 1024 + tid * 4;
        int row = lin >> 6, col = lin & 63;
        float4 qv = *(const float4*)&Q[(q0 + row) * D_MODEL + col];
        sQt[col + 0][row] = qv.x; sQt[col + 1][row] = qv.y;
        sQt[col + 2][row] = qv.z; sQt[col + 3][row] = qv.w;
    }
    if (tid < 64) { sm[tid] = -1e30f; sl[tid] = 0.f; }

    int tx = tid & 15;
    int ty = tid >> 4;
    float acc[4][4];
#pragma unroll
    for (int i = 0; i < 4; i++)
#pragma unroll
        for (int j = 0; j < 4; j++) acc[i][j] = 0.f;

    int kv0 = q0 - WIN; if (kv0 < 0) kv0 = 0;
    int nk  = q0 + 64 - kv0;

    for (int kb = 0; kb < nk; kb += 32) {
        int kbase = kv0 + kb;

        float4 kvec[2], vvec[2];
        int krow[2], kcol[2];
#pragma unroll
        for (int i = 0; i < 2; i++) {
            int lin = i * 1024 + tid * 4;
            krow[i] = lin >> 6; kcol[i] = lin & 63;
            kvec[i] = *(const float4*)&Kp[(kbase + krow[i]) * D_MODEL + kcol[i]];
            vvec[i] = *(const float4*)&Vp[(kbase + krow[i]) * D_MODEL + kcol[i]];
        }
        __syncthreads();
#pragma unroll
        for (int i = 0; i < 2; i++) {
            sKt[kcol[i] + 0][krow[i]] = kvec[i].x;
            sKt[kcol[i] + 1][krow[i]] = kvec[i].y;
            sKt[kcol[i] + 2][krow[i]] = kvec[i].z;
            sKt[kcol[i] + 3][krow[i]] = kvec[i].w;
            *(float4*)&sV[krow[i]][kcol[i]] = vvec[i];
        }
        __syncthreads();

        float sc[4][2] = {{0.f,0.f},{0.f,0.f},{0.f,0.f},{0.f,0.f}};
#pragma unroll
        for (int d = 0; d < 64; d++) {
            float4 qv  = *(const float4*)&sQt[d][ty * 4];
            float2 kv2 = *(const float2*)&sKt[d][tx * 2];
            sc[0][0] += qv.x * kv2.x; sc[0][1] += qv.x * kv2.y;
            sc[1][0] += qv.y * kv2.x; sc[1][1] += qv.y * kv2.y;
            sc[2][0] += qv.z * kv2.x; sc[2][1] += qv.z * kv2.y;
            sc[3][0] += qv.w * kv2.x; sc[3][1] += qv.w * kv2.y;
        }
#pragma unroll
        for (int i = 0; i < 4; i++) {
            int qg = q0 + ty * 4 + i;
#pragma unroll
            for (int j = 0; j < 2; j++) {
                int kg = kbase + tx * 2 + j;
                bool blocked = (kg > qg) || (kg < qg - WIN);
                sP[ty * 4 + i][tx * 2 + j] = blocked ? -1e30f : sc[i][j];
            }
        }
        __syncthreads();

        {
            int rr = tid >> 2, g = tid & 3;
            float v[8]; float mx = -1e30f;
#pragma unroll
            for (int u = 0; u < 8; u++) { v[u] = sP[rr][g * 8 + u]; mx = fmaxf(mx, v[u]); }
            mx = fmaxf(mx, __shfl_xor_sync(0xffffffffu, mx, 1));
            mx = fmaxf(mx, __shfl_xor_sync(0xffffffffu, mx, 2));
            float mold = sm[rr];
            float mnew = fmaxf(mold, mx);
            float sum = 0.f;
#pragma unroll
            for (int u = 0; u < 8; u++) {
                float p = (v[u] < -1e29f) ? 0.f : __expf(v[u] - mnew);
                sP[rr][g * 8 + u] = p;
                sum += p;
            }
            sum += __shfl_xor_sync(0xffffffffu, sum, 1);
            sum += __shfl_xor_sync(0xffffffffu, sum, 2);
            if (g == 0) {
                float scl = __expf(mold - mnew);
                sl[rr] = sl[rr] * scl + sum;
                sm[rr] = mnew;
                sscale[rr] = scl;
            }
        }
        __syncthreads();

#pragma unroll
        for (int i = 0; i < 4; i++) {
            float scl = sscale[ty * 4 + i];
            acc[i][0] *= scl; acc[i][1] *= scl; acc[i][2] *= scl; acc[i][3] *= scl;
        }
#pragma unroll
        for (int k = 0; k < 32; k++) {
            float4 vv = *(const float4*)&sV[k][tx * 4];
#pragma unroll
            for (int i = 0; i < 4; i++) {
                float p = sP[ty * 4 + i][k];
                acc[i][0] += p * vv.x; acc[i][1] += p * vv.y;
                acc[i][2] += p * vv.z; acc[i][3] += p * vv.w;
            }
        }
    }

#pragma unroll
    for (int i = 0; i < 4; i++) {
        int qg = q0 + ty * 4 + i;
        float inv = 1.f / sl[ty * 4 + i];
        float4 o;
        o.x = acc[i][0] * inv; o.y = acc[i][1] * inv;
        o.z = acc[i][2] * inv; o.w = acc[i][3] * inv;
        *(float4*)&g_ao[((size_t)b * SEQ + qg) * D_MODEL + h * DH + tx * 4] = o;
    }
}

// ---------------------------------------------------------------------------
extern "C" void kernel_launch(void* const* d_in, const int* in_sizes, int n_in,
                              void* d_out, int out_size)
{
    const float* x  = (const float*)d_in[0];
    const float* Wq = (const float*)d_in[1];
    const float* bq = (const float*)d_in[2];
    const float* Wk = (const float*)d_in[3];
    const float* bk = (const float*)d_in[4];
    const float* Wv = (const float*)d_in[5];
    const float* bv = (const float*)d_in[6];
    const float* Wo = (const float*)d_in[7];
    const float* bo = (const float*)d_in[8];
    float* out = (float*)d_out;

    cudaFuncSetAttribute(gemm_tc, cudaFuncAttributeMaxDynamicSharedMemorySize, SMEM_DYN);

    const int NX4 = MROWS * D_MODEL / 4;       // 1,048,576
    const int NW4 = D_MODEL * D_MODEL / 4;     // 262,144
    conv_split<<<NX4 / 256, 256>>>(x,  0, NX4);
    conv_split<<<NW4 / 256, 256>>>(Wq, 1, NW4);
    conv_split<<<NW4 / 256, 256>>>(Wk, 2, NW4);
    conv_split<<<NW4 / 256, 256>>>(Wv, 3, NW4);
    conv_split<<<NW4 / 256, 256>>>(Wo, 4, NW4);

    gemm_tc<<<dim3(8, 32, 3), 256, SMEM_DYN>>>(bq, bk, bv, nullptr, 0);

    rope_kernel<<<MROWS, 512>>>();

    dim3 agrid(SEQ / 64, NHEADS, BATCH);
    attn_kernel<<<agrid, 256>>>();

    conv_split<<<NX4 / 256, 256>>>(nullptr, 5, NX4);

    gemm_tc<<<dim3(8, 32, 1), 256, SMEM_DYN>>>(bo, nullptr, nullptr, out, 1);
}

// round 4
// speedup vs baseline: 1.8239x; 1.0430x over previous
#include <cuda_runtime.h>
#include <cuda_bf16.h>
#include <math.h>
#include <stdint.h>

#define D_MODEL 1024
#define NHEADS  16
#define DH      64
#define SEQ     2048
#define BATCH   2
#define WIN     128
#define MROWS   (BATCH * SEQ)   // 4096

// ---------------- scratch (static device memory) ----------------
__device__ float g_q [MROWS * D_MODEL];
__device__ float g_k [MROWS * D_MODEL];
__device__ float g_v [MROWS * D_MODEL];

__device__ __nv_bfloat16 g_xh [MROWS * D_MODEL];
__device__ __nv_bfloat16 g_xl [MROWS * D_MODEL];
__device__ __nv_bfloat16 g_wh [4 * D_MODEL * D_MODEL];
__device__ __nv_bfloat16 g_wl [4 * D_MODEL * D_MODEL];
__device__ __nv_bfloat16 g_aoh[MROWS * D_MODEL];
__device__ __nv_bfloat16 g_aol[MROWS * D_MODEL];

// ---------------- PTX helpers (sm_80-era: valid on sm_100 plain target) ----
__device__ __forceinline__ uint32_t smem_u32(const void* p) {
    uint32_t a;
    asm("{ .reg .u64 t; cvta.to.shared.u64 t, %1; cvt.u32.u64 %0, t; }"
        : "=r"(a) : "l"(p));
    return a;
}
#define CPA16(dst, src) \
    asm volatile("cp.async.cg.shared.global [%0], [%1], 16;" :: "r"(dst), "l"(src))
#define CPA_COMMIT() asm volatile("cp.async.commit_group;" ::: "memory")
#define CPA_WAIT1()  asm volatile("cp.async.wait_group 1;" ::: "memory")
#define CPA_WAIT0()  asm volatile("cp.async.wait_group 0;" ::: "memory")

#define LDM4(r, addr) \
    asm volatile("ldmatrix.sync.aligned.m8n8.x4.shared.b16 {%0,%1,%2,%3}, [%4];" \
        : "=r"((r)[0]), "=r"((r)[1]), "=r"((r)[2]), "=r"((r)[3]) : "r"(addr))

#define MMA16816(acc, a, b0, b1) \
    asm volatile("mma.sync.aligned.m16n8k16.row.col.f32.bf16.bf16.f32 " \
        "{%0,%1,%2,%3}, {%4,%5,%6,%7}, {%8,%9}, {%0,%1,%2,%3};" \
        : "+f"((acc)[0]), "+f"((acc)[1]), "+f"((acc)[2]), "+f"((acc)[3]) \
        : "r"((a)[0]), "r"((a)[1]), "r"((a)[2]), "r"((a)[3]), "r"(b0), "r"(b1))

// ---------------------------------------------------------------------------
// fp32 -> bf16 hi/lo split, all inputs in one launch.
// blocks [0,4096): x ; [4096,8192): W's (1024 blocks each)
// ---------------------------------------------------------------------------
__global__ __launch_bounds__(256)
void conv_all(const float* __restrict__ x,
              const float* __restrict__ Wq, const float* __restrict__ Wk,
              const float* __restrict__ Wv, const float* __restrict__ Wo)
{
    int blk = blockIdx.x;
    const float* src;
    __nv_bfloat16 *hi, *lo;
    int i;
    if (blk < 4096) {
        src = x; hi = g_xh; lo = g_xl;
        i = blk * 256 + threadIdx.x;
    } else {
        int w  = (blk - 4096) >> 10;
        int bb = (blk - 4096) & 1023;
        src = (w == 0) ? Wq : (w == 1) ? Wk : (w == 2) ? Wv : Wo;
        hi = g_wh + (size_t)w * D_MODEL * D_MODEL;
        lo = g_wl + (size_t)w * D_MODEL * D_MODEL;
        i = bb * 256 + threadIdx.x;
    }

    float4 v = ((const float4*)src)[i];
    __nv_bfloat16 h0 = __float2bfloat16(v.x);
    __nv_bfloat16 h1 = __float2bfloat16(v.y);
    __nv_bfloat16 h2 = __float2bfloat16(v.z);
    __nv_bfloat16 h3 = __float2bfloat16(v.w);
    __nv_bfloat162 hh0 = {h0, h1}, hh1 = {h2, h3};
    ((__nv_bfloat162*)hi)[i * 2]     = hh0;
    ((__nv_bfloat162*)hi)[i * 2 + 1] = hh1;
    __nv_bfloat162 ll0 = {__float2bfloat16(v.x - __bfloat162float(h0)),
                          __float2bfloat16(v.y - __bfloat162float(h1))};
    __nv_bfloat162 ll1 = {__float2bfloat16(v.z - __bfloat162float(h2)),
                          __float2bfloat16(v.w - __bfloat162float(h3))};
    ((__nv_bfloat162*)lo)[i * 2]     = ll0;
    ((__nv_bfloat162*)lo)[i * 2 + 1] = ll1;
}

// ---------------------------------------------------------------------------
// mma.sync bf16-split GEMM: C[M,N] = A*W^T + bias, M=4096, N=K=1024.
// 128x128 CTA tile, 8 warps (64x32 each), K-chunks of 32, cp.async 2-stage.
// Tiles per stage: Ah, Al, Bh, Bl (each 128x32 bf16 = 8KB, 64B rows,
// 2-bit XOR swizzle).  2 CTAs/SM (64KB smem + pad per CTA).
// ---------------------------------------------------------------------------
#define TILE_B  8192
#define STAGE_B 32768
#define SMEM_DYN (2 * STAGE_B + 1024)

__global__ __launch_bounds__(256, 2)
void gemm_tc(const float* __restrict__ b0, const float* __restrict__ b1,
             const float* __restrict__ b2, float* __restrict__ out_direct, int mode)
{
    extern __shared__ char dsm_raw[];
    char* sm = (char*)(((uintptr_t)dsm_raw + 1023) & ~(uintptr_t)1023);
    const uint32_t sb = smem_u32(sm);
    const int tid = threadIdx.x, wid = tid >> 5, lane = tid & 31;
    const int bn = blockIdx.x * 128, bm = blockIdx.y * 128, z = blockIdx.z;

    const __nv_bfloat16 *Ah, *Al, *Wh, *Wl;
    const float* bias;
    float* C;
    if (mode == 0) {
        Ah = g_xh; Al = g_xl;
        Wh = g_wh + (size_t)z * D_MODEL * D_MODEL;
        Wl = g_wl + (size_t)z * D_MODEL * D_MODEL;
        bias = (z == 0) ? b0 : ((z == 1) ? b1 : b2);
        C = (z == 0) ? g_q : ((z == 1) ? g_k : g_v);
    } else {
        Ah = g_aoh; Al = g_aol;
        Wh = g_wh + (size_t)3 * D_MODEL * D_MODEL;
        Wl = g_wl + (size_t)3 * D_MODEL * D_MODEL;
        bias = b0;
        C = out_direct;
    }

    // cp.async mapping: thread -> row r = tid/2, 16-col half (tid&1),
    // 2 segments of 8 bf16 (16B units) per tile.
    const int r = tid >> 1;
    const int half = tid & 1;
    const __nv_bfloat16* srcs[4] = {
        Ah + (size_t)(bm + r) * D_MODEL + half * 16,
        Al + (size_t)(bm + r) * D_MODEL + half * 16,
        Wh + (size_t)(bn + r) * D_MODEL + half * 16,
        Wl + (size_t)(bn + r) * D_MODEL + half * 16 };
    uint32_t sts_off[2];
#pragma unroll
    for (int s = 0; s < 2; s++) {
        uint32_t u = (uint32_t)(half * 2 + s);
        sts_off[s] = (uint32_t)r * 64 + ((u ^ ((uint32_t)r & 3)) << 4);
    }

    // warp tile origin: 64x32
    const int wm = (wid & 1) * 64;
    const int wn = (wid >> 1) * 32;

    float acc[4][4][4];
#pragma unroll
    for (int mi = 0; mi < 4; mi++)
#pragma unroll
        for (int nj = 0; nj < 4; nj++)
#pragma unroll
            for (int q = 0; q < 4; q++) acc[mi][nj][q] = 0.f;

    const uint32_t lrow = lane & 15;
    const uint32_t lsel = lane >> 4;   // which 16B unit of the k16

    // prologue: chunk 0 -> stage 0
#pragma unroll
    for (int t = 0; t < 4; t++)
#pragma unroll
        for (int s = 0; s < 2; s++)
            CPA16(sb + t * TILE_B + sts_off[s], srcs[t] + s * 8);
    CPA_COMMIT();

    for (int c = 0; c < 32; c++) {
        if (c + 1 < 32) {
            uint32_t stb = sb + (uint32_t)((c + 1) & 1) * STAGE_B;
#pragma unroll
            for (int t = 0; t < 4; t++)
#pragma unroll
                for (int s = 0; s < 2; s++)
                    CPA16(stb + t * TILE_B + sts_off[s], srcs[t] + (c + 1) * 32 + s * 8);
            CPA_COMMIT();
            CPA_WAIT1();
        } else {
            CPA_WAIT0();
        }
        __syncthreads();

        const uint32_t stg = sb + (uint32_t)(c & 1) * STAGE_B;
#pragma unroll
        for (int kk = 0; kk < 2; kk++) {
            uint32_t bh[2][4], bl[2][4];
#pragma unroll
            for (int jp = 0; jp < 2; jp++) {
                uint32_t rw = (uint32_t)(wn + jp * 16) + lrow;
                uint32_t u  = ((uint32_t)kk * 2 + lsel) ^ (rw & 3);
                uint32_t ab = stg + rw * 64 + (u << 4);
                LDM4(bh[jp], ab + 2 * TILE_B);
                LDM4(bl[jp], ab + 3 * TILE_B);
            }
#pragma unroll
            for (int mi = 0; mi < 4; mi++) {
                uint32_t ra = (uint32_t)(wm + mi * 16) + lrow;
                uint32_t u  = ((uint32_t)kk * 2 + lsel) ^ (ra & 3);
                uint32_t aa = stg + ra * 64 + (u << 4);
                uint32_t ah[4], al[4];
                LDM4(ah, aa);
                LDM4(al, aa + TILE_B);
#pragma unroll
                for (int nj = 0; nj < 4; nj++) {
                    const int jp = nj >> 1, w = nj & 1;
                    MMA16816(acc[mi][nj], ah, bh[jp][w], bh[jp][w + 2]);
                    MMA16816(acc[mi][nj], ah, bl[jp][w], bl[jp][w + 2]);
                    MMA16816(acc[mi][nj], al, bh[jp][w], bh[jp][w + 2]);
                }
            }
        }
        __syncthreads();
    }

    // epilogue
#pragma unroll
    for (int mi = 0; mi < 4; mi++) {
        const int row = bm + wm + mi * 16 + (lane >> 2);
#pragma unroll
        for (int nj = 0; nj < 4; nj++) {
            const int col = bn + wn + nj * 8 + ((lane & 3) << 1);
            float2 o0 = { acc[mi][nj][0] + bias[col], acc[mi][nj][1] + bias[col + 1] };
            float2 o1 = { acc[mi][nj][2] + bias[col], acc[mi][nj][3] + bias[col + 1] };
            *(float2*)&C[(size_t)row * D_MODEL + col]       = o0;
            *(float2*)&C[(size_t)(row + 8) * D_MODEL + col] = o1;
        }
    }
}

// ---------------------------------------------------------------------------
// RoPE (in-place on g_q, g_k) + q scale by Dh^-0.5.
// ---------------------------------------------------------------------------
__global__ __launch_bounds__(512)
void rope_kernel()
{
    int bs = blockIdx.x;
    int s  = bs & (SEQ - 1);
    int h  = threadIdx.x >> 5;
    int j  = threadIdx.x & 31;

    float inv = exp2f(-(float)j * (13.2877123795494f / 32.f));
    float ang = (float)s * inv;
    float sn, cs;
    sincosf(ang, &sn, &cs);

    int base = bs * D_MODEL + h * DH;
    float q1 = g_q[base + j], q2 = g_q[base + j + 32];
    g_q[base + j]      = (q1 * cs - q2 * sn) * 0.125f;
    g_q[base + j + 32] = (q1 * sn + q2 * cs) * 0.125f;
    float k1 = g_k[base + j], k2 = g_k[base + j + 32];
    g_k[base + j]      = k1 * cs - k2 * sn;
    g_k[base + j + 32] = k1 * sn + k2 * cs;
}

// ---------------------------------------------------------------------------
// Sliding-window attention (flash-style, fp32), epilogue writes bf16 hi/lo.
// ---------------------------------------------------------------------------
__global__ __launch_bounds__(256)
void attn_kernel()
{
    __shared__ float sQt[64][68];
    __shared__ float sKt[64][34];
    __shared__ float sV [32][64];
    __shared__ float sP [64][33];
    __shared__ float sm[64], sl[64], sscale[64];

    int tid = threadIdx.x;
    int q0 = blockIdx.x * 64;
    int h  = blockIdx.y;
    int b  = blockIdx.z;

    const float* Q  = g_q + (size_t)b * SEQ * D_MODEL + h * DH;
    const float* Kp = g_k + (size_t)b * SEQ * D_MODEL + h * DH;
    const float* Vp = g_v + (size_t)b * SEQ * D_MODEL + h * DH;

#pragma unroll
    for (int i = 0; i < 4; i++) {
        int lin = i * 1024 + tid * 4;
        int row = lin >> 6, col = lin & 63;
        float4 qv = *(const float4*)&Q[(q0 + row) * D_MODEL + col];
        sQt[col + 0][row] = qv.x; sQt[col + 1][row] = qv.y;
        sQt[col + 2][row] = qv.z; sQt[col + 3][row] = qv.w;
    }
    if (tid < 64) { sm[tid] = -1e30f; sl[tid] = 0.f; }

    int tx = tid & 15;
    int ty = tid >> 4;
    float acc[4][4];
#pragma unroll
    for (int i = 0; i < 4; i++)
#pragma unroll
        for (int j = 0; j < 4; j++) acc[i][j] = 0.f;

    int kv0 = q0 - WIN; if (kv0 < 0) kv0 = 0;
    int nk  = q0 + 64 - kv0;

    for (int kb = 0; kb < nk; kb += 32) {
        int kbase = kv0 + kb;

        float4 kvec[2], vvec[2];
        int krow[2], kcol[2];
#pragma unroll
        for (int i = 0; i < 2; i++) {
            int lin = i * 1024 + tid * 4;
            krow[i] = lin >> 6; kcol[i] = lin & 63;
            kvec[i] = *(const float4*)&Kp[(kbase + krow[i]) * D_MODEL + kcol[i]];
            vvec[i] = *(const float4*)&Vp[(kbase + krow[i]) * D_MODEL + kcol[i]];
        }
        __syncthreads();
#pragma unroll
        for (int i = 0; i < 2; i++) {
            sKt[kcol[i] + 0][krow[i]] = kvec[i].x;
            sKt[kcol[i] + 1][krow[i]] = kvec[i].y;
            sKt[kcol[i] + 2][krow[i]] = kvec[i].z;
            sKt[kcol[i] + 3][krow[i]] = kvec[i].w;
            *(float4*)&sV[krow[i]][kcol[i]] = vvec[i];
        }
        __syncthreads();

        float sc[4][2] = {{0.f,0.f},{0.f,0.f},{0.f,0.f},{0.f,0.f}};
#pragma unroll
        for (int d = 0; d < 64; d++) {
            float4 qv  = *(const float4*)&sQt[d][ty * 4];
            float2 kv2 = *(const float2*)&sKt[d][tx * 2];
            sc[0][0] += qv.x * kv2.x; sc[0][1] += qv.x * kv2.y;
            sc[1][0] += qv.y * kv2.x; sc[1][1] += qv.y * kv2.y;
            sc[2][0] += qv.z * kv2.x; sc[2][1] += qv.z * kv2.y;
            sc[3][0] += qv.w * kv2.x; sc[3][1] += qv.w * kv2.y;
        }
#pragma unroll
        for (int i = 0; i < 4; i++) {
            int qg = q0 + ty * 4 + i;
#pragma unroll
            for (int j = 0; j < 2; j++) {
                int kg = kbase + tx * 2 + j;
                bool blocked = (kg > qg) || (kg < qg - WIN);
                sP[ty * 4 + i][tx * 2 + j] = blocked ? -1e30f : sc[i][j];
            }
        }
        __syncthreads();

        {
            int rr = tid >> 2, g = tid & 3;
            float v[8]; float mx = -1e30f;
#pragma unroll
            for (int u = 0; u < 8; u++) { v[u] = sP[rr][g * 8 + u]; mx = fmaxf(mx, v[u]); }
            mx = fmaxf(mx, __shfl_xor_sync(0xffffffffu, mx, 1));
            mx = fmaxf(mx, __shfl_xor_sync(0xffffffffu, mx, 2));
            float mold = sm[rr];
            float mnew = fmaxf(mold, mx);
            float sum = 0.f;
#pragma unroll
            for (int u = 0; u < 8; u++) {
                float p = (v[u] < -1e29f) ? 0.f : __expf(v[u] - mnew);
                sP[rr][g * 8 + u] = p;
                sum += p;
            }
            sum += __shfl_xor_sync(0xffffffffu, sum, 1);
            sum += __shfl_xor_sync(0xffffffffu, sum, 2);
            if (g == 0) {
                float scl = __expf(mold - mnew);
                sl[rr] = sl[rr] * scl + sum;
                sm[rr] = mnew;
                sscale[rr] = scl;
            }
        }
        __syncthreads();

#pragma unroll
        for (int i = 0; i < 4; i++) {
            float scl = sscale[ty * 4 + i];
            acc[i][0] *= scl; acc[i][1] *= scl; acc[i][2] *= scl; acc[i][3] *= scl;
        }
#pragma unroll
        for (int k = 0; k < 32; k++) {
            float4 vv = *(const float4*)&sV[k][tx * 4];
#pragma unroll
            for (int i = 0; i < 4; i++) {
                float p = sP[ty * 4 + i][k];
                acc[i][0] += p * vv.x; acc[i][1] += p * vv.y;
                acc[i][2] += p * vv.z; acc[i][3] += p * vv.w;
            }
        }
    }

    // epilogue: normalize, split to bf16 hi/lo, write g_aoh/g_aol
#pragma unroll
    for (int i = 0; i < 4; i++) {
        int qg = q0 + ty * 4 + i;
        float inv = 1.f / sl[ty * 4 + i];
        float o[4];
        o[0] = acc[i][0] * inv; o[1] = acc[i][1] * inv;
        o[2] = acc[i][2] * inv; o[3] = acc[i][3] * inv;
        size_t idx = ((size_t)b * SEQ + qg) * D_MODEL + h * DH + tx * 4;
        __nv_bfloat16 hh[4], ll[4];
#pragma unroll
        for (int u = 0; u < 4; u++) {
            hh[u] = __float2bfloat16(o[u]);
            ll[u] = __float2bfloat16(o[u] - __bfloat162float(hh[u]));
        }
        __nv_bfloat162 h01 = {hh[0], hh[1]}, h23 = {hh[2], hh[3]};
        __nv_bfloat162 l01 = {ll[0], ll[1]}, l23 = {ll[2], ll[3]};
        ((__nv_bfloat162*)(g_aoh + idx))[0] = h01;
        ((__nv_bfloat162*)(g_aoh + idx))[1] = h23;
        ((__nv_bfloat162*)(g_aol + idx))[0] = l01;
        ((__nv_bfloat162*)(g_aol + idx))[1] = l23;
    }
}

// ---------------------------------------------------------------------------
extern "C" void kernel_launch(void* const* d_in, const int* in_sizes, int n_in,
                              void* d_out, int out_size)
{
    const float* x  = (const float*)d_in[0];
    const float* Wq = (const float*)d_in[1];
    const float* bq = (const float*)d_in[2];
    const float* Wk = (const float*)d_in[3];
    const float* bk = (const float*)d_in[4];
    const float* Wv = (const float*)d_in[5];
    const float* bv = (const float*)d_in[6];
    const float* Wo = (const float*)d_in[7];
    const float* bo = (const float*)d_in[8];
    float* out = (float*)d_out;

    cudaFuncSetAttribute(gemm_tc, cudaFuncAttributeMaxDynamicSharedMemorySize, SMEM_DYN);

    conv_all<<<8192, 256>>>(x, Wq, Wk, Wv, Wo);

    gemm_tc<<<dim3(8, 32, 3), 256, SMEM_DYN>>>(bq, bk, bv, nullptr, 0);

    rope_kernel<<<MROWS, 512>>>();

    dim3 agrid(SEQ / 64, NHEADS, BATCH);
    attn_kernel<<<agrid, 256>>>();

    gemm_tc<<<dim3(8, 32, 1), 256, SMEM_DYN>>>(bo, nullptr, nullptr, out, 1);
}